// round 1
// baseline (speedup 1.0000x reference)
#include <cuda_runtime.h>

// PhaseEncoding: x (8,4096,512) fp32 in [0, 2pi), phase_bins (9,) fp32.
// out[..., j] = 1.0f if bins[j] <= (x % 2pi) < bins[j+1] else 0.0f
// Pure streaming kernel: 64 MiB read + 512 MiB write -> HBM-write bound.

#define TWO_PI_F 6.2831853071795864769f

__global__ void __launch_bounds__(256)
phase_encoding_kernel(const float* __restrict__ x,
                      const float* __restrict__ bins,
                      float4* __restrict__ out,
                      int n)
{
    int i = blockIdx.x * blockDim.x + threadIdx.x;
    if (i >= n) return;

    // Uniform-address loads -> L1 broadcast; cheap under memory-bound regime.
    const float b0 = __ldg(bins + 0);
    const float b1 = __ldg(bins + 1);
    const float b2 = __ldg(bins + 2);
    const float b3 = __ldg(bins + 3);
    const float b4 = __ldg(bins + 4);
    const float b5 = __ldg(bins + 5);
    const float b6 = __ldg(bins + 6);
    const float b7 = __ldg(bins + 7);
    const float b8 = __ldg(bins + 8);

    float v = __ldg(x + i);
    // Reference: x_norm = x % 2pi (min(x) >= 0 branch). For x in [0, 2pi)
    // this is the identity, but keep fmodf for exact semantic match.
    float vn = fmodf(v, TWO_PI_F);

    float4 lo4, hi4;
    lo4.x = (vn >= b0 && vn < b1) ? 1.0f : 0.0f;
    lo4.y = (vn >= b1 && vn < b2) ? 1.0f : 0.0f;
    lo4.z = (vn >= b2 && vn < b3) ? 1.0f : 0.0f;
    lo4.w = (vn >= b3 && vn < b4) ? 1.0f : 0.0f;
    hi4.x = (vn >= b4 && vn < b5) ? 1.0f : 0.0f;
    hi4.y = (vn >= b5 && vn < b6) ? 1.0f : 0.0f;
    hi4.z = (vn >= b6 && vn < b7) ? 1.0f : 0.0f;
    hi4.w = (vn >= b7 && vn < b8) ? 1.0f : 0.0f;

    // 32 B per thread, contiguous across the warp -> coalesced write stream.
    out[2 * i + 0] = lo4;
    out[2 * i + 1] = hi4;
}

extern "C" void kernel_launch(void* const* d_in, const int* in_sizes, int n_in,
                              void* d_out, int out_size)
{
    const float* x    = (const float*)d_in[0];
    const float* bins = (const float*)d_in[1];
    float4* out = (float4*)d_out;

    int n = in_sizes[0];               // 16,777,216 elements
    int threads = 256;
    int blocks = (n + threads - 1) / threads;

    phase_encoding_kernel<<<blocks, threads>>>(x, bins, out, n);
}